// round 13
// baseline (speedup 1.0000x reference)
#include <cuda_runtime.h>
#include <cstdint>
#include <cstddef>

#define B_ 1024
#define G_ 256
#define K_ 256
#define E_ 64
#define BETA_F 0.05f

// ---------------- scratch (__device__ globals: no runtime allocation) ----------
__device__ float gM  [K_*E_*E_];    // M_k = W_k^T W_k
__device__ float gS6 [K_*E_*E_];    // sum_{j=0..5} A^j
__device__ float gL  [K_*E_*E_];    // chol(R_k), lower, upper zeroed
__device__ float gV  [K_*E_];       // v_k = mu_k W_k
__device__ float gVL [K_*E_];       // vl_k = v_k L_k
__device__ float gMunorm[K_];
__device__ float gD2 [B_*K_];       // 2*(x.mu_k) - ||mu_k||^2
__device__ float gScore[B_*K_];
__device__ int   gKmax[B_];
__device__ float gXh [B_*G_];       // tf32 hi of X
__device__ float gXl [B_*G_];       // tf32 lo of X
__device__ float gWLh[(size_t)K_*G_*E_];   // tf32 hi of WL_k = W_k*L_k
__device__ float gWLl[(size_t)K_*G_*E_];   // tf32 lo

// ---------------- helpers -------------------------------------------------------
__device__ __forceinline__ float tf32r(float x) {
    uint32_t r; asm("cvt.rna.tf32.f32 %0, %1;" : "=r"(r) : "f"(x));
    return __uint_as_float(r);
}
__device__ __forceinline__ void mma_tf32(float* c, const float* a, float b0, float b1) {
    asm volatile(
        "mma.sync.aligned.m16n8k8.row.col.f32.tf32.tf32.f32 "
        "{%0,%1,%2,%3},{%4,%5,%6,%7},{%8,%9},{%0,%1,%2,%3};"
        : "+f"(c[0]), "+f"(c[1]), "+f"(c[2]), "+f"(c[3])
        : "r"(__float_as_uint(a[0])), "r"(__float_as_uint(a[1])),
          "r"(__float_as_uint(a[2])), "r"(__float_as_uint(a[3])),
          "r"(__float_as_uint(b0)),  "r"(__float_as_uint(b1)));
}
__device__ __forceinline__ void cp16(float* dst, const float* src) {
    uint32_t d = (uint32_t)__cvta_generic_to_shared(dst);
    asm volatile("cp.async.cg.shared.global [%0], [%1], 16;" :: "r"(d), "l"(src));
}
#define CP_COMMIT()  asm volatile("cp.async.commit_group;")
#define CP_WAIT(n)   asm volatile("cp.async.wait_group %0;" :: "n"(n))

// ---------------- K0: X -> tf32 hi/lo (row-major, once) -------------------------
__global__ __launch_bounds__(256) void k0_xsplit(const float* __restrict__ X)
{
    int i = (blockIdx.x * 256 + threadIdx.x) * 4;
    float4 v = *(const float4*)&X[i];
    float hx = tf32r(v.x), hy = tf32r(v.y), hz = tf32r(v.z), hw = tf32r(v.w);
    *(float4*)&gXh[i] = make_float4(hx, hy, hz, hw);
    *(float4*)&gXl[i] = make_float4(tf32r(v.x - hx), tf32r(v.y - hy),
                                    tf32r(v.z - hz), tf32r(v.w - hw));
}

// ---------------- K1: per-k  M, v, ||mu_k||^2 ----------------------------------
__global__ __launch_bounds__(256) void k1_prep(const float* __restrict__ mu,
                                               const float* __restrict__ w)
{
    int k = blockIdx.x;
    int t = threadIdx.x;
    __shared__ float Ws[64*64];
    __shared__ float mus[64];
    __shared__ float red[64];
    float acc[16];
#pragma unroll
    for (int i = 0; i < 16; i++) acc[i] = 0.f;
    float vacc = 0.f, mn = 0.f;
    const float* wk = w + (size_t)k * G_ * E_;
    for (int gc = 0; gc < G_; gc += 64) {
        const float* src = wk + (size_t)gc * E_;
        for (int idx = t; idx < 4096; idx += 256) Ws[idx] = src[idx];
        if (t < 64) mus[t] = mu[(size_t)(gc + t) * K_ + k];
        __syncthreads();
#pragma unroll
        for (int r = 0; r < 16; r++) {
            int idx = t + (r << 8);
            int e = idx >> 6, f = idx & 63;
            float a = 0.f;
#pragma unroll 16
            for (int g = 0; g < 64; g++) a += Ws[g*64 + e] * Ws[g*64 + f];
            acc[r] += a;
        }
        if (t < 64) {
            float va = 0.f;
#pragma unroll 16
            for (int g = 0; g < 64; g++) va += mus[g] * Ws[g*64 + t];
            vacc += va;
            mn += mus[t] * mus[t];
        }
        __syncthreads();
    }
    float* Mk = gM + (size_t)k * 4096;
#pragma unroll
    for (int r = 0; r < 16; r++) Mk[t + (r << 8)] = acc[r];
    if (t < 64) { gV[k*E_ + t] = vacc; red[t] = mn; }
    __syncthreads();
    if (t == 0) { float s = 0.f; for (int i = 0; i < 64; i++) s += red[i]; gMunorm[k] = s; }
}

// ---------------- K2a: per-k  S6, R, chol(R)=LL^T -> gL, vl --------------------
__global__ __launch_bounds__(256) void k2a_poly()
{
    int k = blockIdx.x;
    int t = threadIdx.x;
    __shared__ float Ms[64*64];
    __shared__ float Ss[64*64];
    const float* Mk = gM + (size_t)k * 4096;
    for (int idx = t; idx < 4096; idx += 256) {
        Ms[idx] = Mk[idx];
        Ss[idx] = ((idx >> 6) == (idx & 63)) ? 1.f : 0.f;
    }
    __syncthreads();
    for (int it = 0; it < 4; it++) {
        float val[16];
#pragma unroll
        for (int r = 0; r < 16; r++) {
            int idx = t + (r << 8);
            int e = idx >> 6, f = idx & 63;
            float a = 0.f;
#pragma unroll 16
            for (int g = 0; g < 64; g++) a += Ms[e*64 + g] * Ss[g*64 + f];
            float v = (1.f - BETA_F) * Ss[idx] - BETA_F * a;
            if (e == f) v += 1.f;
            val[r] = v;
        }
        __syncthreads();
#pragma unroll
        for (int r = 0; r < 16; r++) Ss[t + (r << 8)] = val[r];
        __syncthreads();
    }
    float ms5[16];
#pragma unroll
    for (int r = 0; r < 16; r++) {
        int idx = t + (r << 8);
        int e = idx >> 6, f = idx & 63;
        float a = 0.f;
#pragma unroll 16
        for (int g = 0; g < 64; g++) a += Ms[e*64 + g] * Ss[g*64 + f];
        ms5[r] = a;
        float s6 = (1.f - BETA_F) * Ss[idx] - BETA_F * a;
        if (e == f) s6 += 1.f;
        gS6[(size_t)k*4096 + idx] = s6;
    }
    __syncthreads();
#pragma unroll
    for (int r = 0; r < 16; r++) Ms[t + (r << 8)] = ms5[r];
    __syncthreads();
    float rv[16];
#pragma unroll
    for (int r = 0; r < 16; r++) {
        int idx = t + (r << 8);
        int e = idx >> 6, f = idx & 63;
        float q = 0.f;
#pragma unroll 16
        for (int g = 0; g < 64; g++) q += Ms[e*64 + g] * Ss[g*64 + f];
        rv[r] = 2.f*BETA_F*Ss[idx] - BETA_F*BETA_F*q;
    }
    __syncthreads();
#pragma unroll
    for (int r = 0; r < 16; r++) Ss[t + (r << 8)] = rv[r];
    __syncthreads();

    // In-place Cholesky (lower) of Ss.
    for (int j = 0; j < 64; j++) {
        if (t == 0) Ss[j*65] = sqrtf(Ss[j*65]);
        __syncthreads();
        float dinv = __frcp_rn(Ss[j*65]);
        if (t > j && t < 64) Ss[t*64 + j] *= dinv;
        __syncthreads();
        for (int idx = t; idx < 4096; idx += 256) {
            int i = idx >> 6, c = idx & 63;
            if (c > j && c <= i) Ss[i*64 + c] -= Ss[i*64 + j] * Ss[c*64 + j];
        }
        __syncthreads();
    }
    for (int idx = t; idx < 4096; idx += 256) {
        int f = idx >> 6, e = idx & 63;
        if (f < e) Ss[idx] = 0.f;
    }
    __syncthreads();

    float* Lk = gL + (size_t)k*4096;
    for (int idx = t; idx < 4096; idx += 256) Lk[idx] = Ss[idx];

    if (t < 64) {   // vl = v * L
        float a = 0.f;
#pragma unroll 16
        for (int f = 0; f < 64; f++) a += gV[k*E_ + f] * Ss[f*64 + t];
        gVL[k*E_ + t] = a;
    }
}

// ---------------- K2b: WL = W*L chunk -> tf32 hi/lo row-major ------------------
// grid (4, 256): 64 g-rows x one k per block.
__global__ __launch_bounds__(256) void k2b_wl(const float* __restrict__ w)
{
    int gc = blockIdx.x * 64;
    int k  = blockIdx.y;
    int t  = threadIdx.x;
    __shared__ float Ls[64*64];
    __shared__ float Ws[64*64];
    const float* Lk = gL + (size_t)k*4096;
    for (int idx = t; idx < 4096; idx += 256) Ls[idx] = Lk[idx];
    const float* src = w + ((size_t)k*G_ + gc)*E_;
    for (int idx = t; idx < 4096; idx += 256) Ws[idx] = src[idx];
    __syncthreads();
#pragma unroll
    for (int r = 0; r < 16; r++) {
        int idx = t + (r << 8);
        int g = idx >> 6, e = idx & 63;
        float a = 0.f;
#pragma unroll 16
        for (int f = 0; f < 64; f++) a += Ws[g*64 + f] * Ls[f*64 + e];
        size_t o = ((size_t)k*G_ + gc + g)*E_ + e;
        float h = tf32r(a);
        gWLh[o] = h;
        gWLl[o] = tf32r(a - h);
    }
}

// ---------------- KD: gD2[b][k] = 2*(x_b.mu_k) - ||mu_k||^2 --------------------
__global__ __launch_bounds__(256) void kD_dots(const float* __restrict__ X,
                                               const float* __restrict__ mu)
{
    const int b0 = blockIdx.x * 64;
    const int kc = blockIdx.y * 64;
    const int t  = threadIdx.x;
    const int tx = t & 15;
    const int ty = t >> 4;
    __shared__ float XsT[32*68];
    __shared__ float Ms[32*64];
    float acc[4][4];
#pragma unroll
    for (int i = 0; i < 4; i++)
#pragma unroll
        for (int l = 0; l < 4; l++) acc[i][l] = 0.f;

    for (int gc = 0; gc < G_; gc += 32) {
        for (int idx = t; idx < 2048; idx += 256) {
            int i = idx >> 5, j = idx & 31;
            XsT[j*68 + i] = X[(size_t)(b0 + i)*G_ + gc + j];
        }
        for (int idx = t; idx < 2048; idx += 256) {
            int j = idx >> 6, e = idx & 63;
            Ms[idx] = mu[(size_t)(gc + j)*K_ + kc + e];
        }
        __syncthreads();
#pragma unroll
        for (int j = 0; j < 32; j++) {
            float4 a = *(const float4*)&XsT[j*68 + ty*4];
            float4 m = *(const float4*)&Ms [j*64 + tx*4];
            acc[0][0] += a.x*m.x; acc[0][1] += a.x*m.y; acc[0][2] += a.x*m.z; acc[0][3] += a.x*m.w;
            acc[1][0] += a.y*m.x; acc[1][1] += a.y*m.y; acc[1][2] += a.y*m.z; acc[1][3] += a.y*m.w;
            acc[2][0] += a.z*m.x; acc[2][1] += a.z*m.y; acc[2][2] += a.z*m.z; acc[2][3] += a.z*m.w;
            acc[3][0] += a.w*m.x; acc[3][1] += a.w*m.y; acc[3][2] += a.w*m.z; acc[3][3] += a.w*m.w;
        }
        __syncthreads();
    }
#pragma unroll
    for (int i = 0; i < 4; i++)
#pragma unroll
        for (int l = 0; l < 4; l++) {
            int kk = kc + tx*4 + l;
            gD2[(size_t)(b0 + ty*4 + i)*K_ + kk] = 2.f*acc[i][l] - gMunorm[kk];
        }
}

// ---------------- K3: tf32 MMA GEMM C = X*WL, score = gD2 + ||C - vl||^2 -------
// grid (16, 256): 64 b x 1 k. 256 thr = 8 warps: wb = wid&3 (16-row quad),
// we = wid>>2 (32-col half). cp.async double buffer; smem frags validated in R9.
// Buffer layout (floats): Xh[64*36] Xl[64*36] Wh[32*72] Wl[32*72] = 9216/buf.
__global__ __launch_bounds__(256) void k3_score()
{
    extern __shared__ float S[];
    const int k  = blockIdx.y;
    const int b0 = blockIdx.x * 64;
    const int t  = threadIdx.x;
    const int lane = t & 31, wid = t >> 5;
    const int wb = wid & 3, we = wid >> 2;
    const int gID = lane >> 2, tig = lane & 3;

    float* vls = S + 18432;
    float* qp  = S + 18496;
    if (t < 64) vls[t] = gVL[k*E_ + t];

    auto issue = [&](int gi) {
        float* xb = S + (gi & 1) * 9216;
        float* xl = xb + 2304;
        float* wh = xb + 4608;
        float* wl = xb + 6912;
        int gc = gi * 32;
#pragma unroll
        for (int s = 0; s < 2; s++) {
            int idx = t + s*256;                 // 512: X rows 64 x 8 chunks
            int row = idx >> 3, ch = (idx & 7) << 2;
            cp16(&xb[row*36 + ch], &gXh[(size_t)(b0 + row)*G_ + gc + ch]);
            cp16(&xl[row*36 + ch], &gXl[(size_t)(b0 + row)*G_ + gc + ch]);
        }
#pragma unroll
        for (int s = 0; s < 2; s++) {
            int idx = t + s*256;                 // 512: W rows 32 x 16 chunks
            int row = idx >> 4, ch = (idx & 15) << 2;
            size_t o = ((size_t)k*G_ + gc + row)*E_ + ch;
            cp16(&wh[row*72 + ch], &gWLh[o]);
            cp16(&wl[row*72 + ch], &gWLl[o]);
        }
    };

    float acc[4][4];
#pragma unroll
    for (int i = 0; i < 4; i++)
#pragma unroll
        for (int l = 0; l < 4; l++) acc[i][l] = 0.f;

    issue(0); CP_COMMIT();
    for (int gi = 0; gi < 8; gi++) {
        if (gi < 7) { issue(gi + 1); CP_COMMIT(); CP_WAIT(1); }
        else        { CP_WAIT(0); }
        __syncthreads();
        const float* xh = S + (gi & 1) * 9216;
        const float* xl = xh + 2304;
        const float* wh = xh + 4608;
        const float* wl = xh + 6912;
#pragma unroll
        for (int ks = 0; ks < 4; ks++) {
            int ar = wb*16 + gID;
            int ac = ks*8 + tig;
            float ah[4], al[4];
            ah[0] = xh[ar*36 + ac];     ah[1] = xh[(ar+8)*36 + ac];
            ah[2] = xh[ar*36 + ac + 4]; ah[3] = xh[(ar+8)*36 + ac + 4];
            al[0] = xl[ar*36 + ac];     al[1] = xl[(ar+8)*36 + ac];
            al[2] = xl[ar*36 + ac + 4]; al[3] = xl[(ar+8)*36 + ac + 4];
#pragma unroll
            for (int ni = 0; ni < 4; ni++) {
                int bc = we*32 + ni*8 + gID;
                int br = ks*8 + tig;
                float bh0 = wh[br*72 + bc], bh1 = wh[(br+4)*72 + bc];
                float bl0 = wl[br*72 + bc], bl1 = wl[(br+4)*72 + bc];
                mma_tf32(acc[ni], ah, bh0, bh1);   // hi*hi
                mma_tf32(acc[ni], ah, bl0, bl1);   // hi*lo
                mma_tf32(acc[ni], al, bh0, bh1);   // lo*hi
            }
        }
        __syncthreads();
    }

    // epilogue: p_b = sum over owned cols of (C - vl)^2, reduce over tig (xor 1,2)
    float p1 = 0.f, p2 = 0.f;
#pragma unroll
    for (int ni = 0; ni < 4; ni++) {
        int col = we*32 + ni*8 + 2*tig;
        float v0 = vls[col], v1 = vls[col + 1];
        float d0 = acc[ni][0] - v0, d1 = acc[ni][1] - v1;
        float d2 = acc[ni][2] - v0, d3 = acc[ni][3] - v1;
        p1 += d0*d0 + d1*d1;
        p2 += d2*d2 + d3*d3;
    }
    p1 += __shfl_xor_sync(0xffffffffu, p1, 1);
    p1 += __shfl_xor_sync(0xffffffffu, p1, 2);
    p2 += __shfl_xor_sync(0xffffffffu, p2, 1);
    p2 += __shfl_xor_sync(0xffffffffu, p2, 2);

    int r1 = wb*16 + gID, r2 = r1 + 8;
    if (we == 0 && tig == 0) { qp[r1] = p1; qp[r2] = p2; }
    __syncthreads();
    if (we == 1 && tig == 0) {
        gScore[(size_t)(b0 + r1)*K_ + k] = gD2[(size_t)(b0 + r1)*K_ + k] + qp[r1] + p1;
        gScore[(size_t)(b0 + r2)*K_ + k] = gD2[(size_t)(b0 + r2)*K_ + k] + qp[r2] + p2;
    }
}

// ---------------- K4: argmax over k (first-max tie-break) ----------------------
__global__ __launch_bounds__(256) void k4_argmax()
{
    int b = blockIdx.x;
    int t = threadIdx.x;
    __shared__ float sv[256];
    __shared__ int   si[256];
    sv[t] = gScore[(size_t)b * K_ + t];
    si[t] = t;
    __syncthreads();
    for (int s = 128; s > 0; s >>= 1) {
        if (t < s) {
            float v2 = sv[t + s]; int i2 = si[t + s];
            if (v2 > sv[t] || (v2 == sv[t] && i2 < si[t])) { sv[t] = v2; si[t] = i2; }
        }
        __syncthreads();
    }
    if (t == 0) gKmax[b] = si[0];
}

// ---------------- K5: decode winner: y = beta*u*S6*W^T + mu_k ------------------
__global__ __launch_bounds__(256) void k5_decode(const float* __restrict__ X,
                                                 const float* __restrict__ mu,
                                                 const float* __restrict__ w,
                                                 float* __restrict__ y)
{
    int b = blockIdx.x;
    int t = threadIdx.x;
    __shared__ float upart[4][64];
    __shared__ float us[64];
    __shared__ float z6[64];
    int k = gKmax[b];
    const float* wk = w + (size_t)k * G_ * E_;

    {
        int e = t & 63, gq = t >> 6;
        float a = 0.f;
        const float* xb = X + (size_t)b * G_;
#pragma unroll 16
        for (int g = gq*64; g < gq*64 + 64; g++) a += xb[g] * wk[(size_t)g*E_ + e];
        upart[gq][e] = a;
    }
    __syncthreads();
    if (t < 64) us[t] = upart[0][t] + upart[1][t] + upart[2][t] + upart[3][t] - gV[k*E_ + t];
    __syncthreads();
    if (t < 64) {
        const float* S6k = gS6 + (size_t)k * 4096;
        float a = 0.f;
#pragma unroll 16
        for (int f = 0; f < 64; f++) a += us[f] * S6k[f*64 + t];
        z6[t] = BETA_F * a;
    }
    __syncthreads();
    {
        int g = t;
        float a = 0.f;
        const float* wg = wk + (size_t)g * E_;
#pragma unroll
        for (int e = 0; e < 64; e++) a += z6[e] * wg[e];
        y[(size_t)b * G_ + g] = a + mu[(size_t)g * K_ + k];
    }
}

// ---------------- launch --------------------------------------------------------
extern "C" void kernel_launch(void* const* d_in, const int* in_sizes, int n_in,
                              void* d_out, int out_size)
{
    const float* X  = (const float*)d_in[0];   // images (B,G)
    const float* mu = (const float*)d_in[1];   // (G,K)
    const float* w  = (const float*)d_in[2];   // (K,G,E)
    float* y = (float*)d_out;                  // (B,G)

    const int smem3 = (18432 + 128) * 4;       // 74240 B dynamic smem for k3
    cudaFuncSetAttribute(k3_score, cudaFuncAttributeMaxDynamicSharedMemorySize, smem3);

    k0_xsplit<<<B_*G_/1024, 256>>>(X);
    k1_prep<<<K_, 256>>>(mu, w);
    k2a_poly<<<K_, 256>>>();
    dim3 g2b(4, K_);
    k2b_wl<<<g2b, 256>>>(w);
    dim3 gD(B_/64, K_/64);
    kD_dots<<<gD, 256>>>(X, mu);
    dim3 g3(B_/64, K_);
    k3_score<<<g3, 256, smem3>>>();
    k4_argmax<<<B_, 256>>>();
    k5_decode<<<B_, 256>>>(X, mu, w, y);
}

// round 14
// speedup vs baseline: 1.2047x; 1.2047x over previous
#include <cuda_runtime.h>
#include <cstdint>
#include <cstddef>

#define B_ 1024
#define G_ 256
#define K_ 256
#define E_ 64
#define BETA_F 0.05f

// ---------------- scratch (__device__ globals: no runtime allocation) ----------
__device__ float gM [K_*E_*E_];   // M_k = W_k^T W_k
__device__ float gS6[K_*E_*E_];   // sum_{j=0..5} A^j
__device__ float gR [K_*E_*E_];   // 2b*S5 - b^2*S5*M*S5
__device__ float gV [K_*E_];      // v_k = mu_k W_k
__device__ float gMunorm[K_];
__device__ float gD2[B_*K_];      // 2*(x.mu_k) - ||mu_k||^2
__device__ float gScore[B_*K_];
__device__ int   gKmax[B_];
// X as mma-A fragments, tf32 hi/lo: [bb=64][g8=32][lane=32][hi4 lo4]   (2 MB)
__device__ float gXF[(size_t)64*32*32*8];
// W as mma-B fragments, tf32 hi/lo: [k][g8=32][ni=8][lane=32][bh0,bh1,bl0,bl1] (33.5 MB)
__device__ float gWF[(size_t)K_*32*8*32*4];

// ---------------- helpers -------------------------------------------------------
__device__ __forceinline__ float tf32r(float x) {
    uint32_t r; asm("cvt.rna.tf32.f32 %0, %1;" : "=r"(r) : "f"(x));
    return __uint_as_float(r);
}
__device__ __forceinline__ void mma_tf32(float* c, const float* a, float b0, float b1) {
    asm volatile(
        "mma.sync.aligned.m16n8k8.row.col.f32.tf32.tf32.f32 "
        "{%0,%1,%2,%3},{%4,%5,%6,%7},{%8,%9},{%0,%1,%2,%3};"
        : "+f"(c[0]), "+f"(c[1]), "+f"(c[2]), "+f"(c[3])
        : "r"(__float_as_uint(a[0])), "r"(__float_as_uint(a[1])),
          "r"(__float_as_uint(a[2])), "r"(__float_as_uint(a[3])),
          "r"(__float_as_uint(b0)),  "r"(__float_as_uint(b1)));
}
__device__ __forceinline__ void cp16(float* dst, const float* src) {
    uint32_t d = (uint32_t)__cvta_generic_to_shared(dst);
    asm volatile("cp.async.cg.shared.global [%0], [%1], 16;" :: "r"(d), "l"(src));
}
#define CP_COMMIT()  asm volatile("cp.async.commit_group;")
#define CP_WAIT(n)   asm volatile("cp.async.wait_group %0;" :: "n"(n))

// ---------------- K0: X -> A-fragment hi/lo layout (validated in R10) ----------
__global__ __launch_bounds__(256) void k0_xsplit(const float* __restrict__ X)
{
    int bb = blockIdx.x;           // 16-row block of B
    int t = threadIdx.x;
    __shared__ float Xs[16*260];
    for (int idx = t; idx < 4096; idx += 256) {
        int r = idx >> 8, c = idx & 255;
        Xs[r*260 + c] = X[(size_t)(bb*16 + r)*G_ + c];
    }
    __syncthreads();
    int lane = t & 31, wq = t >> 5;
    int gID = lane >> 2, tig = lane & 3;
#pragma unroll
    for (int q = 0; q < 4; q++) {
        int gg = wq*4 + q;
        int c0 = gg*8 + tig;
        float x0 = Xs[gID*260 + c0];
        float x1 = Xs[(gID+8)*260 + c0];
        float x2 = Xs[gID*260 + c0 + 4];
        float x3 = Xs[(gID+8)*260 + c0 + 4];
        float h0 = tf32r(x0), h1 = tf32r(x1), h2 = tf32r(x2), h3 = tf32r(x3);
        float* dst = gXF + ((size_t)(bb*32 + gg)*32 + lane)*8;
        *(float4*)dst       = make_float4(h0, h1, h2, h3);
        *(float4*)(dst + 4) = make_float4(tf32r(x0 - h0), tf32r(x1 - h1),
                                          tf32r(x2 - h2), tf32r(x3 - h3));
    }
}

// ---------------- K1: per-k  M, v, ||mu_k||^2 ----------------------------------
__global__ __launch_bounds__(256) void k1_prep(const float* __restrict__ mu,
                                               const float* __restrict__ w)
{
    int k = blockIdx.x;
    int t = threadIdx.x;
    __shared__ float Ws[64*64];
    __shared__ float mus[64];
    __shared__ float red[64];
    float acc[16];
#pragma unroll
    for (int i = 0; i < 16; i++) acc[i] = 0.f;
    float vacc = 0.f, mn = 0.f;
    const float* wk = w + (size_t)k * G_ * E_;
    for (int gc = 0; gc < G_; gc += 64) {
        const float* src = wk + (size_t)gc * E_;
        for (int idx = t; idx < 4096; idx += 256) Ws[idx] = src[idx];
        if (t < 64) mus[t] = mu[(size_t)(gc + t) * K_ + k];
        __syncthreads();
#pragma unroll
        for (int r = 0; r < 16; r++) {
            int idx = t + (r << 8);
            int e = idx >> 6, f = idx & 63;
            float a = 0.f;
#pragma unroll 16
            for (int g = 0; g < 64; g++) a += Ws[g*64 + e] * Ws[g*64 + f];
            acc[r] += a;
        }
        if (t < 64) {
            float va = 0.f;
#pragma unroll 16
            for (int g = 0; g < 64; g++) va += mus[g] * Ws[g*64 + t];
            vacc += va;
            mn += mus[t] * mus[t];
        }
        __syncthreads();
    }
    float* Mk = gM + (size_t)k * 4096;
#pragma unroll
    for (int r = 0; r < 16; r++) Mk[t + (r << 8)] = acc[r];
    if (t < 64) { gV[k*E_ + t] = vacc; red[t] = mn; }
    __syncthreads();
    if (t == 0) { float s = 0.f; for (int i = 0; i < 64; i++) s += red[i]; gMunorm[k] = s; }
}

// ---------------- K2: per-k  S6 and R ------------------------------------------
__global__ __launch_bounds__(256) void k2_poly()
{
    int k = blockIdx.x;
    int t = threadIdx.x;
    __shared__ float Ms[64*64];
    __shared__ float Ss[64*64];
    const float* Mk = gM + (size_t)k * 4096;
    for (int idx = t; idx < 4096; idx += 256) {
        Ms[idx] = Mk[idx];
        Ss[idx] = ((idx >> 6) == (idx & 63)) ? 1.f : 0.f;
    }
    __syncthreads();
    for (int it = 0; it < 4; it++) {
        float val[16];
#pragma unroll
        for (int r = 0; r < 16; r++) {
            int idx = t + (r << 8);
            int e = idx >> 6, f = idx & 63;
            float a = 0.f;
#pragma unroll 16
            for (int g = 0; g < 64; g++) a += Ms[e*64 + g] * Ss[g*64 + f];
            float v = (1.f - BETA_F) * Ss[idx] - BETA_F * a;
            if (e == f) v += 1.f;
            val[r] = v;
        }
        __syncthreads();
#pragma unroll
        for (int r = 0; r < 16; r++) Ss[t + (r << 8)] = val[r];
        __syncthreads();
    }
    float ms5[16];
#pragma unroll
    for (int r = 0; r < 16; r++) {
        int idx = t + (r << 8);
        int e = idx >> 6, f = idx & 63;
        float a = 0.f;
#pragma unroll 16
        for (int g = 0; g < 64; g++) a += Ms[e*64 + g] * Ss[g*64 + f];
        ms5[r] = a;
        float s6 = (1.f - BETA_F) * Ss[idx] - BETA_F * a;
        if (e == f) s6 += 1.f;
        gS6[(size_t)k*4096 + idx] = s6;
    }
    __syncthreads();
#pragma unroll
    for (int r = 0; r < 16; r++) Ms[t + (r << 8)] = ms5[r];
    __syncthreads();
#pragma unroll
    for (int r = 0; r < 16; r++) {
        int idx = t + (r << 8);
        int e = idx >> 6, f = idx & 63;
        float q = 0.f;
#pragma unroll 16
        for (int g = 0; g < 64; g++) q += Ms[e*64 + g] * Ss[g*64 + f];
        gR[(size_t)k*4096 + idx] = 2.f*BETA_F*Ss[idx] - BETA_F*BETA_F*q;
    }
}

// ---------------- K2w: w -> B-fragment hi/lo layout (elementwise split) --------
// grid (4, 256): 64 g-rows x one k per block. Layout validated in R10/R12.
__global__ __launch_bounds__(256) void k2w_wfrag(const float* __restrict__ w)
{
    int gc = blockIdx.x * 64;
    int k  = blockIdx.y;
    int t  = threadIdx.x;
    __shared__ float Ws[64*64];
    const float* src = w + ((size_t)k*G_ + gc)*E_;
    for (int idx = t; idx < 4096; idx += 256) Ws[idx] = src[idx];
    __syncthreads();
    int lane = t & 31, wq = t >> 5;
    int gID = lane >> 2, tig = lane & 3;
    int g8 = (gc >> 3) + wq;
    float* dstbase = gWF + ((size_t)k*32 + g8)*8*32*4;
#pragma unroll
    for (int ni = 0; ni < 8; ni++) {
        int col = ni*8 + gID;
        float v0 = Ws[(wq*8 + tig)*64 + col];
        float v1 = Ws[(wq*8 + tig + 4)*64 + col];
        float h0 = tf32r(v0), h1 = tf32r(v1);
        *(float4*)(dstbase + (ni*32 + lane)*4) =
            make_float4(h0, h1, tf32r(v0 - h0), tf32r(v1 - h1));
    }
}

// ---------------- KD: gD2[b][k] = 2*(x_b.mu_k) - ||mu_k||^2 --------------------
__global__ __launch_bounds__(256) void kD_dots(const float* __restrict__ X,
                                               const float* __restrict__ mu)
{
    const int b0 = blockIdx.x * 64;
    const int kc = blockIdx.y * 64;
    const int t  = threadIdx.x;
    const int tx = t & 15;
    const int ty = t >> 4;
    __shared__ float XsT[32*68];
    __shared__ float Ms[32*64];
    float acc[4][4];
#pragma unroll
    for (int i = 0; i < 4; i++)
#pragma unroll
        for (int l = 0; l < 4; l++) acc[i][l] = 0.f;

    for (int gc = 0; gc < G_; gc += 32) {
        for (int idx = t; idx < 2048; idx += 256) {
            int i = idx >> 5, j = idx & 31;
            XsT[j*68 + i] = X[(size_t)(b0 + i)*G_ + gc + j];
        }
        for (int idx = t; idx < 2048; idx += 256) {
            int j = idx >> 6, e = idx & 63;
            Ms[idx] = mu[(size_t)(gc + j)*K_ + kc + e];
        }
        __syncthreads();
#pragma unroll
        for (int j = 0; j < 32; j++) {
            float4 a = *(const float4*)&XsT[j*68 + ty*4];
            float4 m = *(const float4*)&Ms [j*64 + tx*4];
            acc[0][0] += a.x*m.x; acc[0][1] += a.x*m.y; acc[0][2] += a.x*m.z; acc[0][3] += a.x*m.w;
            acc[1][0] += a.y*m.x; acc[1][1] += a.y*m.y; acc[1][2] += a.y*m.z; acc[1][3] += a.y*m.w;
            acc[2][0] += a.z*m.x; acc[2][1] += a.z*m.y; acc[2][2] += a.z*m.z; acc[2][3] += a.z*m.w;
            acc[3][0] += a.w*m.x; acc[3][1] += a.w*m.y; acc[3][2] += a.w*m.z; acc[3][3] += a.w*m.w;
        }
        __syncthreads();
    }
#pragma unroll
    for (int i = 0; i < 4; i++)
#pragma unroll
        for (int l = 0; l < 4; l++) {
            int kk = kc + tx*4 + l;
            gD2[(size_t)(b0 + ty*4 + i)*K_ + kk] = 2.f*acc[i][l] - gMunorm[kk];
        }
}

// ---------------- K3: frag-fed 3xTF32 MMA GEMM + scalar quadform ---------------
// grid (16, 256): 64 b x 1 k, 256 thr = 8 warps (wb 16-row quad, we 32-col half).
// Mainloop per warp per g8: 2+4 LDS.128 -> 12 MMA. cp.async double buffer (4 g8/buf).
// Then u = C - v staged to UsT, quadform T=U*R (scalar), score = gD2 + uRu.
__global__ __launch_bounds__(256) void k3_score()
{
    extern __shared__ float S[];
    const int k  = blockIdx.y;
    const int b0 = blockIdx.x * 64;
    const int t  = threadIdx.x;
    const int lane = t & 31, wid = t >> 5;
    const int wb = wid & 3, we = wid >> 2;
    const int gID = lane >> 2, tig = lane & 3;

    float* vls = S + 16384;
    if (t < 64) vls[t] = gV[k*E_ + t];

    auto issue = [&](int gi) {
        float* buf = S + (gi & 1)*8192;
        int gc8 = gi*4;
        // X frags: [q][bb][lane][8] -> 1024 cp16
#pragma unroll
        for (int s = 0; s < 4; s++) {
            int idx = t + s*256;
            int q = idx >> 8, rem = idx & 255;
            int bb = rem >> 6, j = rem & 63;
            int ln = j >> 1, half = (j & 1) << 2;
            cp16(buf + q*1024 + bb*256 + ln*8 + half,
                 gXF + (((size_t)(blockIdx.x*4 + bb)*32 + gc8 + q)*32 + ln)*8 + half);
        }
        // W frags: [q][ni][lane][4] -> 1024 cp16
#pragma unroll
        for (int s = 0; s < 4; s++) {
            int idx = t + s*256;
            int q = idx >> 8, rem = idx & 255;
            int ni = rem >> 5, ln = rem & 31;
            cp16(buf + 4096 + q*1024 + ni*128 + ln*4,
                 gWF + (((size_t)k*32 + gc8 + q)*8*32*4 + (ni*32 + ln)*4));
        }
    };

    float acc[4][4];
#pragma unroll
    for (int i = 0; i < 4; i++)
#pragma unroll
        for (int l = 0; l < 4; l++) acc[i][l] = 0.f;

    issue(0); CP_COMMIT();
    for (int gi = 0; gi < 8; gi++) {
        if (gi < 7) { issue(gi + 1); CP_COMMIT(); CP_WAIT(1); }
        else        { CP_WAIT(0); }
        __syncthreads();
        const float* buf = S + (gi & 1)*8192;
#pragma unroll
        for (int q = 0; q < 4; q++) {
            const float* xf = buf + q*1024 + wb*256 + lane*8;
            float4 ah4 = *(const float4*)xf;
            float4 al4 = *(const float4*)(xf + 4);
            float ah[4] = {ah4.x, ah4.y, ah4.z, ah4.w};
            float al[4] = {al4.x, al4.y, al4.z, al4.w};
#pragma unroll
            for (int ni2 = 0; ni2 < 4; ni2++) {
                float4 bv = *(const float4*)(buf + 4096 + q*1024 + (we*4 + ni2)*128 + lane*4);
                mma_tf32(acc[ni2], ah, bv.x, bv.y);   // hi*hi
                mma_tf32(acc[ni2], ah, bv.z, bv.w);   // hi*lo
                mma_tf32(acc[ni2], al, bv.x, bv.y);   // lo*hi
            }
        }
        __syncthreads();
    }

    // ---- stage u = C - v into UsT[e][b] (both buffers dead now) ----
    float* UsT = S;            // 64*68 = 4352
    float* Rs  = S + 4608;     // 4096
    float* qp  = S + 8704;     // 64
    {
        int r1 = wb*16 + gID, r2 = r1 + 8;
#pragma unroll
        for (int ni2 = 0; ni2 < 4; ni2++) {
            int c0 = we*32 + ni2*8 + 2*tig, c1 = c0 + 1;
            float v0 = vls[c0], v1 = vls[c1];
            UsT[c0*68 + r1] = acc[ni2][0] - v0;
            UsT[c1*68 + r1] = acc[ni2][1] - v1;
            UsT[c0*68 + r2] = acc[ni2][2] - v0;
            UsT[c1*68 + r2] = acc[ni2][3] - v1;
        }
    }
    // load R tile
#pragma unroll
    for (int s = 0; s < 4; s++) {
        int i4 = (t + s*256) << 2;
        cp16(Rs + i4, gR + (size_t)k*4096 + i4);
    }
    CP_COMMIT(); CP_WAIT(0);
    __syncthreads();

    // ---- quadform: T = U*R, p_b = sum_e T[b][e]*U[b][e] ----
    const int tx = t & 15, ty = t >> 4;
    float tacc[4][4];
#pragma unroll
    for (int i = 0; i < 4; i++)
#pragma unroll
        for (int l = 0; l < 4; l++) tacc[i][l] = 0.f;
#pragma unroll 8
    for (int f = 0; f < 64; f++) {
        float4 a  = *(const float4*)&UsT[f*68 + ty*4];
        float4 rr = *(const float4*)&Rs [f*64 + tx*4];
        tacc[0][0] += a.x*rr.x; tacc[0][1] += a.x*rr.y; tacc[0][2] += a.x*rr.z; tacc[0][3] += a.x*rr.w;
        tacc[1][0] += a.y*rr.x; tacc[1][1] += a.y*rr.y; tacc[1][2] += a.y*rr.z; tacc[1][3] += a.y*rr.w;
        tacc[2][0] += a.z*rr.x; tacc[2][1] += a.z*rr.y; tacc[2][2] += a.z*rr.z; tacc[2][3] += a.z*rr.w;
        tacc[3][0] += a.w*rr.x; tacc[3][1] += a.w*rr.y; tacc[3][2] += a.w*rr.z; tacc[3][3] += a.w*rr.w;
    }
    float p[4] = {0.f, 0.f, 0.f, 0.f};
#pragma unroll
    for (int l = 0; l < 4; l++) {
        float4 uu = *(const float4*)&UsT[(tx*4 + l)*68 + ty*4];
        p[0] += tacc[0][l]*uu.x; p[1] += tacc[1][l]*uu.y;
        p[2] += tacc[2][l]*uu.z; p[3] += tacc[3][l]*uu.w;
    }
#pragma unroll
    for (int i = 0; i < 4; i++) {
#pragma unroll
        for (int ofs = 8; ofs > 0; ofs >>= 1)
            p[i] += __shfl_down_sync(0xffffffffu, p[i], ofs, 16);
    }
    if (tx == 0) {
#pragma unroll
        for (int i = 0; i < 4; i++) qp[ty*4 + i] = p[i];
    }
    __syncthreads();
    if (t < 64)
        gScore[(size_t)(b0 + t)*K_ + k] = gD2[(size_t)(b0 + t)*K_ + k] + qp[t];
}

// ---------------- K4: argmax over k (first-max tie-break) ----------------------
__global__ __launch_bounds__(256) void k4_argmax()
{
    int b = blockIdx.x;
    int t = threadIdx.x;
    __shared__ float sv[256];
    __shared__ int   si[256];
    sv[t] = gScore[(size_t)b * K_ + t];
    si[t] = t;
    __syncthreads();
    for (int s = 128; s > 0; s >>= 1) {
        if (t < s) {
            float v2 = sv[t + s]; int i2 = si[t + s];
            if (v2 > sv[t] || (v2 == sv[t] && i2 < si[t])) { sv[t] = v2; si[t] = i2; }
        }
        __syncthreads();
    }
    if (t == 0) gKmax[b] = si[0];
}

// ---------------- K5: decode winner: y = beta*u*S6*W^T + mu_k ------------------
__global__ __launch_bounds__(256) void k5_decode(const float* __restrict__ X,
                                                 const float* __restrict__ mu,
                                                 const float* __restrict__ w,
                                                 float* __restrict__ y)
{
    int b = blockIdx.x;
    int t = threadIdx.x;
    __shared__ float upart[4][64];
    __shared__ float us[64];
    __shared__ float z6[64];
    int k = gKmax[b];
    const float* wk = w + (size_t)k * G_ * E_;

    {
        int e = t & 63, gq = t >> 6;
        float a = 0.f;
        const float* xb = X + (size_t)b * G_;
#pragma unroll 16
        for (int g = gq*64; g < gq*64 + 64; g++) a += xb[g] * wk[(size_t)g*E_ + e];
        upart[gq][e] = a;
    }
    __syncthreads();
    if (t < 64) us[t] = upart[0][t] + upart[1][t] + upart[2][t] + upart[3][t] - gV[k*E_ + t];
    __syncthreads();
    if (t < 64) {
        const float* S6k = gS6 + (size_t)k * 4096;
        float a = 0.f;
#pragma unroll 16
        for (int f = 0; f < 64; f++) a += us[f] * S6k[f*64 + t];
        z6[t] = BETA_F * a;
    }
    __syncthreads();
    {
        int g = t;
        float a = 0.f;
        const float* wg = wk + (size_t)g * E_;
#pragma unroll
        for (int e = 0; e < 64; e++) a += z6[e] * wg[e];
        y[(size_t)b * G_ + g] = a + mu[(size_t)g * K_ + k];
    }
}

// ---------------- launch --------------------------------------------------------
extern "C" void kernel_launch(void* const* d_in, const int* in_sizes, int n_in,
                              void* d_out, int out_size)
{
    const float* X  = (const float*)d_in[0];   // images (B,G)
    const float* mu = (const float*)d_in[1];   // (G,K)
    const float* w  = (const float*)d_in[2];   // (K,G,E)
    float* y = (float*)d_out;                  // (B,G)

    const int smem3 = 16448 * 4;               // 65792 B dynamic smem for k3
    cudaFuncSetAttribute(k3_score, cudaFuncAttributeMaxDynamicSharedMemorySize, smem3);

    k0_xsplit<<<64, 256>>>(X);
    k1_prep<<<K_, 256>>>(mu, w);
    k2_poly<<<K_, 256>>>();
    dim3 g2w(4, K_);
    k2w_wfrag<<<g2w, 256>>>(w);
    dim3 gD(B_/64, K_/64);
    kD_dots<<<gD, 256>>>(X, mu);
    dim3 g3(B_/64, K_);
    k3_score<<<g3, 256, smem3>>>();
    k4_argmax<<<B_, 256>>>();
    k5_decode<<<B_, 256>>>(X, mu, w, y);
}

// round 15
// speedup vs baseline: 1.5611x; 1.2958x over previous
#include <cuda_runtime.h>
#include <cstdint>
#include <cstddef>

#define B_ 1024
#define G_ 256
#define K_ 256
#define E_ 64
#define BETA_F 0.05f

// ---------------- scratch (__device__ globals: no runtime allocation) ----------
__device__ float gS6[K_*E_*E_];   // sum_{j=0..5} A^j
__device__ float gR [K_*E_*E_];   // 2b*S5 - b^2*S5*M*S5
__device__ float gV [K_*E_];      // v_k = mu_k W_k
__device__ float gMunorm[K_];
__device__ float gD2[B_*K_];      // 2*(x.mu_k) - ||mu_k||^2
__device__ float gScore[B_*K_];
__device__ int   gKmax[B_];
// X as mma-A fragments, tf32 hi/lo: [bb=64][g8=32][lane=32][hi4 lo4]   (2 MB)
__device__ float gXF[(size_t)64*32*32*8];
// W as mma-B fragments, tf32 hi/lo: [k][g8=32][ni=8][lane=32][bh0,bh1,bl0,bl1] (33.5 MB)
__device__ float gWF[(size_t)K_*32*8*32*4];

// ---------------- helpers -------------------------------------------------------
__device__ __forceinline__ float tf32r(float x) {
    uint32_t r; asm("cvt.rna.tf32.f32 %0, %1;" : "=r"(r) : "f"(x));
    return __uint_as_float(r);
}
__device__ __forceinline__ void mma_tf32(float* c, const float* a, float b0, float b1) {
    asm volatile(
        "mma.sync.aligned.m16n8k8.row.col.f32.tf32.tf32.f32 "
        "{%0,%1,%2,%3},{%4,%5,%6,%7},{%8,%9},{%0,%1,%2,%3};"
        : "+f"(c[0]), "+f"(c[1]), "+f"(c[2]), "+f"(c[3])
        : "r"(__float_as_uint(a[0])), "r"(__float_as_uint(a[1])),
          "r"(__float_as_uint(a[2])), "r"(__float_as_uint(a[3])),
          "r"(__float_as_uint(b0)),  "r"(__float_as_uint(b1)));
}
__device__ __forceinline__ void cp16(float* dst, const float* src) {
    uint32_t d = (uint32_t)__cvta_generic_to_shared(dst);
    asm volatile("cp.async.cg.shared.global [%0], [%1], 16;" :: "r"(d), "l"(src));
}
#define CP_COMMIT()  asm volatile("cp.async.commit_group;")
#define CP_WAIT(n)   asm volatile("cp.async.wait_group %0;" :: "n"(n))

// ---------------- K0: X -> A-fragment hi/lo layout (validated R10/R13) ---------
__global__ __launch_bounds__(256) void k0_xsplit(const float* __restrict__ X)
{
    int bb = blockIdx.x;           // 16-row block of B
    int t = threadIdx.x;
    __shared__ float Xs[16*260];
    for (int idx = t; idx < 4096; idx += 256) {
        int r = idx >> 8, c = idx & 255;
        Xs[r*260 + c] = X[(size_t)(bb*16 + r)*G_ + c];
    }
    __syncthreads();
    int lane = t & 31, wq = t >> 5;
    int gID = lane >> 2, tig = lane & 3;
#pragma unroll
    for (int q = 0; q < 4; q++) {
        int gg = wq*4 + q;
        int c0 = gg*8 + tig;
        float x0 = Xs[gID*260 + c0];
        float x1 = Xs[(gID+8)*260 + c0];
        float x2 = Xs[gID*260 + c0 + 4];
        float x3 = Xs[(gID+8)*260 + c0 + 4];
        float h0 = tf32r(x0), h1 = tf32r(x1), h2 = tf32r(x2), h3 = tf32r(x3);
        float* dst = gXF + ((size_t)(bb*32 + gg)*32 + lane)*8;
        *(float4*)dst       = make_float4(h0, h1, h2, h3);
        *(float4*)(dst + 4) = make_float4(tf32r(x0 - h0), tf32r(x1 - h1),
                                          tf32r(x2 - h2), tf32r(x3 - h3));
    }
}

// ---------------- K12: fused prep: M (smem), v, ||mu||^2, S6, R ----------------
// All 64x64x64 matmul phases use 4x4 register micro-tiles + float4 smem loads.
// M is bitwise-symmetric (identical term order), so M[e][g] is read as the
// contiguous float4 M[g][e-range]. ms5 is stored TRANSPOSED so the R phase
// needs no symmetry assumption. Element-wise math identical to old k1+k2.
__global__ __launch_bounds__(256) void k12_prep(const float* __restrict__ mu,
                                                const float* __restrict__ w)
{
    int k = blockIdx.x;
    int t = threadIdx.x;
    const int tx = t & 15;   // f-group: f = tx*4..tx*4+3
    const int ty = t >> 4;   // e-group: e = ty*4..ty*4+3
    __shared__ float BufA[64*64];   // M, later ms5^T
    __shared__ float BufB[64*64];   // Ws chunks, later S
    __shared__ float mus[64];
    __shared__ float red[64];

    // ---- phase 1: M = W^T W (acc in regs), v = mu.W, ||mu||^2 ----
    float acc[4][4];
#pragma unroll
    for (int i = 0; i < 4; i++)
#pragma unroll
        for (int j = 0; j < 4; j++) acc[i][j] = 0.f;
    float vacc = 0.f, mn = 0.f;
    const float* wk = w + (size_t)k * G_ * E_;
    for (int gc = 0; gc < G_; gc += 64) {
        const float* src = wk + (size_t)gc * E_;
        for (int idx = t; idx < 4096; idx += 256) BufB[idx] = src[idx];
        if (t < 64) mus[t] = mu[(size_t)(gc + t) * K_ + k];
        __syncthreads();
#pragma unroll 8
        for (int g = 0; g < 64; g++) {
            float4 a = *(const float4*)&BufB[g*64 + ty*4];
            float4 b = *(const float4*)&BufB[g*64 + tx*4];
            acc[0][0] += a.x*b.x; acc[0][1] += a.x*b.y; acc[0][2] += a.x*b.z; acc[0][3] += a.x*b.w;
            acc[1][0] += a.y*b.x; acc[1][1] += a.y*b.y; acc[1][2] += a.y*b.z; acc[1][3] += a.y*b.w;
            acc[2][0] += a.z*b.x; acc[2][1] += a.z*b.y; acc[2][2] += a.z*b.z; acc[2][3] += a.z*b.w;
            acc[3][0] += a.w*b.x; acc[3][1] += a.w*b.y; acc[3][2] += a.w*b.z; acc[3][3] += a.w*b.w;
        }
        if (t < 64) {
            float va = 0.f;
#pragma unroll 16
            for (int g = 0; g < 64; g++) va += mus[g] * BufB[g*64 + t];
            vacc += va;
            mn += mus[t] * mus[t];
        }
        __syncthreads();
    }
    // M -> BufA; identity -> BufB; v/munorm out
#pragma unroll
    for (int i = 0; i < 4; i++)
        *(float4*)&BufA[(ty*4 + i)*64 + tx*4] =
            make_float4(acc[i][0], acc[i][1], acc[i][2], acc[i][3]);
    for (int idx = t; idx < 4096; idx += 256)
        BufB[idx] = ((idx >> 6) == (idx & 63)) ? 1.f : 0.f;
    if (t < 64) { gV[k*E_ + t] = vacc; red[t] = mn; }
    __syncthreads();
    if (t == 0) { float s = 0.f; for (int i = 0; i < 64; i++) s += red[i]; gMunorm[k] = s; }
    __syncthreads();

    // ---- phase 2: 4 poly iters  S <- (1-b)S - b*(M*S) + I ----
    for (int it = 0; it < 4; it++) {
        float val[4][4];
#pragma unroll
        for (int i = 0; i < 4; i++)
#pragma unroll
            for (int j = 0; j < 4; j++) val[i][j] = 0.f;
#pragma unroll 8
        for (int g = 0; g < 64; g++) {
            float4 a = *(const float4*)&BufA[g*64 + ty*4];   // = M[e][g], bitwise sym
            float4 b = *(const float4*)&BufB[g*64 + tx*4];   // S[g][f]
            val[0][0] += a.x*b.x; val[0][1] += a.x*b.y; val[0][2] += a.x*b.z; val[0][3] += a.x*b.w;
            val[1][0] += a.y*b.x; val[1][1] += a.y*b.y; val[1][2] += a.y*b.z; val[1][3] += a.y*b.w;
            val[2][0] += a.z*b.x; val[2][1] += a.z*b.y; val[2][2] += a.z*b.z; val[2][3] += a.z*b.w;
            val[3][0] += a.w*b.x; val[3][1] += a.w*b.y; val[3][2] += a.w*b.z; val[3][3] += a.w*b.w;
        }
        float nv[4][4];
#pragma unroll
        for (int i = 0; i < 4; i++) {
            float4 old = *(const float4*)&BufB[(ty*4 + i)*64 + tx*4];
            int e = ty*4 + i;
            nv[i][0] = (1.f - BETA_F)*old.x - BETA_F*val[i][0] + ((e == tx*4    ) ? 1.f : 0.f);
            nv[i][1] = (1.f - BETA_F)*old.y - BETA_F*val[i][1] + ((e == tx*4 + 1) ? 1.f : 0.f);
            nv[i][2] = (1.f - BETA_F)*old.z - BETA_F*val[i][2] + ((e == tx*4 + 2) ? 1.f : 0.f);
            nv[i][3] = (1.f - BETA_F)*old.w - BETA_F*val[i][3] + ((e == tx*4 + 3) ? 1.f : 0.f);
        }
        __syncthreads();
#pragma unroll
        for (int i = 0; i < 4; i++)
            *(float4*)&BufB[(ty*4 + i)*64 + tx*4] =
                make_float4(nv[i][0], nv[i][1], nv[i][2], nv[i][3]);
        __syncthreads();
    }

    // ---- phase 3: ms5 = M*S5 ; S6 = (1-b)S5 - b*ms5 + I -> gmem ----
    {
        float val[4][4];
#pragma unroll
        for (int i = 0; i < 4; i++)
#pragma unroll
            for (int j = 0; j < 4; j++) val[i][j] = 0.f;
#pragma unroll 8
        for (int g = 0; g < 64; g++) {
            float4 a = *(const float4*)&BufA[g*64 + ty*4];
            float4 b = *(const float4*)&BufB[g*64 + tx*4];
            val[0][0] += a.x*b.x; val[0][1] += a.x*b.y; val[0][2] += a.x*b.z; val[0][3] += a.x*b.w;
            val[1][0] += a.y*b.x; val[1][1] += a.y*b.y; val[1][2] += a.y*b.z; val[1][3] += a.y*b.w;
            val[2][0] += a.z*b.x; val[2][1] += a.z*b.y; val[2][2] += a.z*b.z; val[2][3] += a.z*b.w;
            val[3][0] += a.w*b.x; val[3][1] += a.w*b.y; val[3][2] += a.w*b.z; val[3][3] += a.w*b.w;
        }
        float* S6k = gS6 + (size_t)k*4096;
#pragma unroll
        for (int i = 0; i < 4; i++) {
            float4 s5 = *(const float4*)&BufB[(ty*4 + i)*64 + tx*4];
            int e = ty*4 + i;
            float4 s6;
            s6.x = (1.f - BETA_F)*s5.x - BETA_F*val[i][0] + ((e == tx*4    ) ? 1.f : 0.f);
            s6.y = (1.f - BETA_F)*s5.y - BETA_F*val[i][1] + ((e == tx*4 + 1) ? 1.f : 0.f);
            s6.z = (1.f - BETA_F)*s5.z - BETA_F*val[i][2] + ((e == tx*4 + 2) ? 1.f : 0.f);
            s6.w = (1.f - BETA_F)*s5.w - BETA_F*val[i][3] + ((e == tx*4 + 3) ? 1.f : 0.f);
            *(float4*)&S6k[(ty*4 + i)*64 + tx*4] = s6;
        }
        __syncthreads();
        // store ms5 TRANSPOSED into BufA: BufA[f][e] = ms5[e][f]
#pragma unroll
        for (int i = 0; i < 4; i++)
#pragma unroll
            for (int j = 0; j < 4; j++)
                BufA[(tx*4 + j)*64 + ty*4 + i] = val[i][j];
        __syncthreads();
    }

    // ---- phase 4: q = ms5*S5 ; R = 2b*S5 - b^2*q -> gmem ----
    {
        float val[4][4];
#pragma unroll
        for (int i = 0; i < 4; i++)
#pragma unroll
            for (int j = 0; j < 4; j++) val[i][j] = 0.f;
#pragma unroll 8
        for (int g = 0; g < 64; g++) {
            float4 a = *(const float4*)&BufA[g*64 + ty*4];   // = ms5[e][g] via transpose
            float4 b = *(const float4*)&BufB[g*64 + tx*4];   // S5[g][f]
            val[0][0] += a.x*b.x; val[0][1] += a.x*b.y; val[0][2] += a.x*b.z; val[0][3] += a.x*b.w;
            val[1][0] += a.y*b.x; val[1][1] += a.y*b.y; val[1][2] += a.y*b.z; val[1][3] += a.y*b.w;
            val[2][0] += a.z*b.x; val[2][1] += a.z*b.y; val[2][2] += a.z*b.z; val[2][3] += a.z*b.w;
            val[3][0] += a.w*b.x; val[3][1] += a.w*b.y; val[3][2] += a.w*b.z; val[3][3] += a.w*b.w;
        }
        float* Rk = gR + (size_t)k*4096;
#pragma unroll
        for (int i = 0; i < 4; i++) {
            float4 s5 = *(const float4*)&BufB[(ty*4 + i)*64 + tx*4];
            float4 r;
            r.x = 2.f*BETA_F*s5.x - BETA_F*BETA_F*val[i][0];
            r.y = 2.f*BETA_F*s5.y - BETA_F*BETA_F*val[i][1];
            r.z = 2.f*BETA_F*s5.z - BETA_F*BETA_F*val[i][2];
            r.w = 2.f*BETA_F*s5.w - BETA_F*BETA_F*val[i][3];
            *(float4*)&Rk[(ty*4 + i)*64 + tx*4] = r;
        }
    }
}

// ---------------- K2w: w -> B-fragment hi/lo layout (validated R13) ------------
__global__ __launch_bounds__(256) void k2w_wfrag(const float* __restrict__ w)
{
    int gc = blockIdx.x * 64;
    int k  = blockIdx.y;
    int t  = threadIdx.x;
    __shared__ float Ws[64*64];
    const float* src = w + ((size_t)k*G_ + gc)*E_;
    for (int idx = t; idx < 4096; idx += 256) Ws[idx] = src[idx];
    __syncthreads();
    int lane = t & 31, wq = t >> 5;
    int gID = lane >> 2, tig = lane & 3;
    int g8 = (gc >> 3) + wq;
    float* dstbase = gWF + ((size_t)k*32 + g8)*8*32*4;
#pragma unroll
    for (int ni = 0; ni < 8; ni++) {
        int col = ni*8 + gID;
        float v0 = Ws[(wq*8 + tig)*64 + col];
        float v1 = Ws[(wq*8 + tig + 4)*64 + col];
        float h0 = tf32r(v0), h1 = tf32r(v1);
        *(float4*)(dstbase + (ni*32 + lane)*4) =
            make_float4(h0, h1, tf32r(v0 - h0), tf32r(v1 - h1));
    }
}

// ---------------- KD: gD2[b][k] = 2*(x_b.mu_k) - ||mu_k||^2 --------------------
__global__ __launch_bounds__(256) void kD_dots(const float* __restrict__ X,
                                               const float* __restrict__ mu)
{
    const int b0 = blockIdx.x * 64;
    const int kc = blockIdx.y * 64;
    const int t  = threadIdx.x;
    const int tx = t & 15;
    const int ty = t >> 4;
    __shared__ float XsT[32*68];
    __shared__ float Ms[32*64];
    float acc[4][4];
#pragma unroll
    for (int i = 0; i < 4; i++)
#pragma unroll
        for (int l = 0; l < 4; l++) acc[i][l] = 0.f;

    for (int gc = 0; gc < G_; gc += 32) {
        for (int idx = t; idx < 2048; idx += 256) {
            int i = idx >> 5, j = idx & 31;
            XsT[j*68 + i] = X[(size_t)(b0 + i)*G_ + gc + j];
        }
        for (int idx = t; idx < 2048; idx += 256) {
            int j = idx >> 6, e = idx & 63;
            Ms[idx] = mu[(size_t)(gc + j)*K_ + kc + e];
        }
        __syncthreads();
#pragma unroll
        for (int j = 0; j < 32; j++) {
            float4 a = *(const float4*)&XsT[j*68 + ty*4];
            float4 m = *(const float4*)&Ms [j*64 + tx*4];
            acc[0][0] += a.x*m.x; acc[0][1] += a.x*m.y; acc[0][2] += a.x*m.z; acc[0][3] += a.x*m.w;
            acc[1][0] += a.y*m.x; acc[1][1] += a.y*m.y; acc[1][2] += a.y*m.z; acc[1][3] += a.y*m.w;
            acc[2][0] += a.z*m.x; acc[2][1] += a.z*m.y; acc[2][2] += a.z*m.z; acc[2][3] += a.z*m.w;
            acc[3][0] += a.w*m.x; acc[3][1] += a.w*m.y; acc[3][2] += a.w*m.z; acc[3][3] += a.w*m.w;
        }
        __syncthreads();
    }
#pragma unroll
    for (int i = 0; i < 4; i++)
#pragma unroll
        for (int l = 0; l < 4; l++) {
            int kk = kc + tx*4 + l;
            gD2[(size_t)(b0 + ty*4 + i)*K_ + kk] = 2.f*acc[i][l] - gMunorm[kk];
        }
}

// ---------------- K3: frag-fed 3xTF32 MMA GEMM + scalar quadform (R14) ---------
__global__ __launch_bounds__(256) void k3_score()
{
    extern __shared__ float S[];
    const int k  = blockIdx.y;
    const int b0 = blockIdx.x * 64;
    const int t  = threadIdx.x;
    const int lane = t & 31, wid = t >> 5;
    const int wb = wid & 3, we = wid >> 2;
    const int gID = lane >> 2, tig = lane & 3;

    float* vls = S + 16384;
    if (t < 64) vls[t] = gV[k*E_ + t];

    auto issue = [&](int gi) {
        float* buf = S + (gi & 1)*8192;
        int gc8 = gi*4;
#pragma unroll
        for (int s = 0; s < 4; s++) {
            int idx = t + s*256;
            int q = idx >> 8, rem = idx & 255;
            int bb = rem >> 6, j = rem & 63;
            int ln = j >> 1, half = (j & 1) << 2;
            cp16(buf + q*1024 + bb*256 + ln*8 + half,
                 gXF + (((size_t)(blockIdx.x*4 + bb)*32 + gc8 + q)*32 + ln)*8 + half);
        }
#pragma unroll
        for (int s = 0; s < 4; s++) {
            int idx = t + s*256;
            int q = idx >> 8, rem = idx & 255;
            int ni = rem >> 5, ln = rem & 31;
            cp16(buf + 4096 + q*1024 + ni*128 + ln*4,
                 gWF + (((size_t)k*32 + gc8 + q)*8*32*4 + (ni*32 + ln)*4));
        }
    };

    float acc[4][4];
#pragma unroll
    for (int i = 0; i < 4; i++)
#pragma unroll
        for (int l = 0; l < 4; l++) acc[i][l] = 0.f;

    issue(0); CP_COMMIT();
    for (int gi = 0; gi < 8; gi++) {
        if (gi < 7) { issue(gi + 1); CP_COMMIT(); CP_WAIT(1); }
        else        { CP_WAIT(0); }
        __syncthreads();
        const float* buf = S + (gi & 1)*8192;
#pragma unroll
        for (int q = 0; q < 4; q++) {
            const float* xf = buf + q*1024 + wb*256 + lane*8;
            float4 ah4 = *(const float4*)xf;
            float4 al4 = *(const float4*)(xf + 4);
            float ah[4] = {ah4.x, ah4.y, ah4.z, ah4.w};
            float al[4] = {al4.x, al4.y, al4.z, al4.w};
#pragma unroll
            for (int ni2 = 0; ni2 < 4; ni2++) {
                float4 bv = *(const float4*)(buf + 4096 + q*1024 + (we*4 + ni2)*128 + lane*4);
                mma_tf32(acc[ni2], ah, bv.x, bv.y);   // hi*hi
                mma_tf32(acc[ni2], ah, bv.z, bv.w);   // hi*lo
                mma_tf32(acc[ni2], al, bv.x, bv.y);   // lo*hi
            }
        }
        __syncthreads();
    }

    // ---- stage u = C - v into UsT[e][b] ----
    float* UsT = S;            // 64*68
    float* Rs  = S + 4608;     // 4096
    float* qp  = S + 8704;     // 64
    {
        int r1 = wb*16 + gID, r2 = r1 + 8;
#pragma unroll
        for (int ni2 = 0; ni2 < 4; ni2++) {
            int c0 = we*32 + ni2*8 + 2*tig, c1 = c0 + 1;
            float v0 = vls[c0], v1 = vls[c1];
            UsT[c0*68 + r1] = acc[ni2][0] - v0;
            UsT[c1*68 + r1] = acc[ni2][1] - v1;
            UsT[c0*68 + r2] = acc[ni2][2] - v0;
            UsT[c1*68 + r2] = acc[ni2][3] - v1;
        }
    }
#pragma unroll
    for (int s = 0; s < 4; s++) {
        int i4 = (t + s*256) << 2;
        cp16(Rs + i4, gR + (size_t)k*4096 + i4);
    }
    CP_COMMIT(); CP_WAIT(0);
    __syncthreads();

    // ---- quadform: T = U*R, p_b = sum_e T[b][e]*U[b][e] ----
    const int tx = t & 15, ty = t >> 4;
    float tacc[4][4];
#pragma unroll
    for (int i = 0; i < 4; i++)
#pragma unroll
        for (int l = 0; l < 4; l++) tacc[i][l] = 0.f;
#pragma unroll 8
    for (int f = 0; f < 64; f++) {
        float4 a  = *(const float4*)&UsT[f*68 + ty*4];
        float4 rr = *(const float4*)&Rs [f*64 + tx*4];
        tacc[0][0] += a.x*rr.x; tacc[0][1] += a.x*rr.y; tacc[0][2] += a.x*rr.z; tacc[0][3] += a.x*rr.w;
        tacc[1][0] += a.y*rr.x; tacc[1][1] += a.y*rr.y; tacc[1][2] += a.y*rr.z; tacc[1][3] += a.y*rr.w;
        tacc[2][0] += a.z*rr.x; tacc[2][1] += a.z*rr.y; tacc[2][2] += a.z*rr.z; tacc[2][3] += a.z*rr.w;
        tacc[3][0] += a.w*rr.x; tacc[3][1] += a.w*rr.y; tacc[3][2] += a.w*rr.z; tacc[3][3] += a.w*rr.w;
    }
    float p[4] = {0.f, 0.f, 0.f, 0.f};
#pragma unroll
    for (int l = 0; l < 4; l++) {
        float4 uu = *(const float4*)&UsT[(tx*4 + l)*68 + ty*4];
        p[0] += tacc[0][l]*uu.x; p[1] += tacc[1][l]*uu.y;
        p[2] += tacc[2][l]*uu.z; p[3] += tacc[3][l]*uu.w;
    }
#pragma unroll
    for (int i = 0; i < 4; i++) {
#pragma unroll
        for (int ofs = 8; ofs > 0; ofs >>= 1)
            p[i] += __shfl_down_sync(0xffffffffu, p[i], ofs, 16);
    }
    if (tx == 0) {
#pragma unroll
        for (int i = 0; i < 4; i++) qp[ty*4 + i] = p[i];
    }
    __syncthreads();
    if (t < 64)
        gScore[(size_t)(b0 + t)*K_ + k] = gD2[(size_t)(b0 + t)*K_ + k] + qp[t];
}

// ---------------- K4: argmax over k (first-max tie-break) ----------------------
__global__ __launch_bounds__(256) void k4_argmax()
{
    int b = blockIdx.x;
    int t = threadIdx.x;
    __shared__ float sv[256];
    __shared__ int   si[256];
    sv[t] = gScore[(size_t)b * K_ + t];
    si[t] = t;
    __syncthreads();
    for (int s = 128; s > 0; s >>= 1) {
        if (t < s) {
            float v2 = sv[t + s]; int i2 = si[t + s];
            if (v2 > sv[t] || (v2 == sv[t] && i2 < si[t])) { sv[t] = v2; si[t] = i2; }
        }
        __syncthreads();
    }
    if (t == 0) gKmax[b] = si[0];
}

// ---------------- K5: decode winner: y = beta*u*S6*W^T + mu_k ------------------
__global__ __launch_bounds__(256) void k5_decode(const float* __restrict__ X,
                                                 const float* __restrict__ mu,
                                                 const float* __restrict__ w,
                                                 float* __restrict__ y)
{
    int b = blockIdx.x;
    int t = threadIdx.x;
    __shared__ float upart[4][64];
    __shared__ float us[64];
    __shared__ float z6[64];
    int k = gKmax[b];
    const float* wk = w + (size_t)k * G_ * E_;

    {
        int e = t & 63, gq = t >> 6;
        float a = 0.f;
        const float* xb = X + (size_t)b * G_;
#pragma unroll 16
        for (int g = gq*64; g < gq*64 + 64; g++) a += xb[g] * wk[(size_t)g*E_ + e];
        upart[gq][e] = a;
    }
    __syncthreads();
    if (t < 64) us[t] = upart[0][t] + upart[1][t] + upart[2][t] + upart[3][t] - gV[k*E_ + t];
    __syncthreads();
    if (t < 64) {
        const float* S6k = gS6 + (size_t)k * 4096;
        float a = 0.f;
#pragma unroll 16
        for (int f = 0; f < 64; f++) a += us[f] * S6k[f*64 + t];
        z6[t] = BETA_F * a;
    }
    __syncthreads();
    {
        int g = t;
        float a = 0.f;
        const float* wg = wk + (size_t)g * E_;
#pragma unroll
        for (int e = 0; e < 64; e++) a += z6[e] * wg[e];
        y[(size_t)b * G_ + g] = a + mu[(size_t)g * K_ + k];
    }
}

// ---------------- launch --------------------------------------------------------
extern "C" void kernel_launch(void* const* d_in, const int* in_sizes, int n_in,
                              void* d_out, int out_size)
{
    const float* X  = (const float*)d_in[0];   // images (B,G)
    const float* mu = (const float*)d_in[1];   // (G,K)
    const float* w  = (const float*)d_in[2];   // (K,G,E)
    float* y = (float*)d_out;                  // (B,G)

    const int smem3 = 16448 * 4;               // 65792 B dynamic smem for k3
    cudaFuncSetAttribute(k3_score, cudaFuncAttributeMaxDynamicSharedMemorySize, smem3);

    k0_xsplit<<<64, 256>>>(X);
    k12_prep<<<K_, 256>>>(mu, w);
    dim3 g2w(4, K_);
    k2w_wfrag<<<g2w, 256>>>(w);
    dim3 gD(B_/64, K_/64);
    kD_dots<<<gD, 256>>>(X, mu);
    dim3 g3(B_/64, K_);
    k3_score<<<g3, 256, smem3>>>();
    k4_argmax<<<B_, 256>>>();
    k5_decode<<<B_, 256>>>(X, mu, w, y);
}